// round 14
// baseline (speedup 1.0000x reference)
#include <cuda_runtime.h>
#include <cuda_bf16.h>

#define BATCH   16384
#define EMBED   64
#define N_EDGES 524288
#define FULL    0xffffffffu
#define MLPGRID 592

// Scratch: zero-initialized at module load; the MLP tail re-zeroes exactly
// the rows it consumed, so every launch/replay starts from zeros.
__device__ float g_scratch[BATCH * EMBED + BATCH];
#define G_ACC g_scratch
#define G_CNT (g_scratch + BATCH * EMBED)

// Empty kernel: shifts launch parity so ncu's fixed "-s 5 -c 1" capture
// lands on agg_kernel (launch order d,agg,d,mlp -> index 5 == agg).
__global__ void dummy_kernel() {}

// ---------------------------------------------------------------------------
// Kernel 1 (R9 — proven): warp owns 32 consecutive edges; ids coalesced
// (.cs) + shfl broadcast; 8 independent 256B feature-row loads in flight
// (.cg); register run-compression on sorted seg_ids, atomic flush on change.
// ---------------------------------------------------------------------------
__global__ void agg_kernel(const int*   __restrict__ neigh_ids,
                           const int*   __restrict__ seg_ids,
                           const float* __restrict__ features) {
    const int warp = (blockIdx.x * blockDim.x + threadIdx.x) >> 5;
    const int lane = threadIdx.x & 31;
    const int e0 = warp * 32;

    const int my_seg = __ldcs(&seg_ids[e0 + lane]);
    const int my_nid = __ldcs(&neigh_ids[e0 + lane]);

    const float2* __restrict__ feats2 = (const float2*)features;

    float2 acc = make_float2(0.0f, 0.0f);
    int cur = __shfl_sync(FULL, my_seg, 0);
    int runlen = 0;

    #pragma unroll
    for (int c = 0; c < 32; c += 8) {
        int    n[8], s[8];
        float2 v[8];
        #pragma unroll
        for (int u = 0; u < 8; ++u) n[u] = __shfl_sync(FULL, my_nid, c + u);
        #pragma unroll
        for (int u = 0; u < 8; ++u)
            v[u] = __ldcg(&feats2[(size_t)n[u] * 32 + lane]);  // L2-only
        #pragma unroll
        for (int u = 0; u < 8; ++u) s[u] = __shfl_sync(FULL, my_seg, c + u);
        #pragma unroll
        for (int u = 0; u < 8; ++u) {
            if (s[u] != cur) {            // warp-uniform (s is broadcast)
                atomicAdd(&G_ACC[cur * EMBED + 2 * lane],     acc.x);
                atomicAdd(&G_ACC[cur * EMBED + 2 * lane + 1], acc.y);
                if (lane == 0) atomicAdd(&G_CNT[cur], (float)runlen);
                acc = make_float2(0.0f, 0.0f);
                cur = s[u];
                runlen = 0;
            }
            acc.x += v[u].x;
            acc.y += v[u].y;
            ++runlen;
        }
    }
    atomicAdd(&G_ACC[cur * EMBED + 2 * lane],     acc.x);
    atomicAdd(&G_ACC[cur * EMBED + 2 * lane + 1], acc.y);
    if (lane == 0) atomicAdd(&G_CNT[cur], (float)runlen);
}

// ---------------------------------------------------------------------------
// Kernel 2: self gather + mean + [self|neigh] @ w1^T + b1, relu.
// Depth-1 pipeline (R10 proven shape) + deferred mean-divide (load path
// ships raw G_ACC; k-groups 2,3 = neigh half scaled at partial stage) +
// consumer tail zeroing. launch_bounds(256,4) caps regs at 64 -> 4 blk/SM.
// ---------------------------------------------------------------------------
__global__ void __launch_bounds__(256, 4)
mlp_kernel(const int*   __restrict__ nodes,
           const float* __restrict__ features,
           const float* __restrict__ w1,
           const float* __restrict__ b1,
           float*       __restrict__ out) {
    __shared__ union {
        float w1s[64 * 129];                        // staging (prologue only)
        struct {
            __align__(16) float comb[2][4][128];    // double-buffered concat
            float part[4][64 * 5];                  // stride-5 padded partials
            float invs[2][4];                       // per-row 1/max(cnt,1)
        } run;
    } sm;
    __shared__ float b1s[64];

    const int tid = threadIdx.x;
    const int g = tid >> 6;                         // k-group 0..3 (warp-uni)
    const int j = tid & 63;                         // output dim
    const int r = g;                                // row for fill/writeback

    for (int idx = tid; idx < 64 * 128; idx += 256) {
        const int jj = idx >> 7;
        const int kk = idx & 127;
        sm.w1s[jj * 129 + kk] = w1[idx];            // w1 row-major (64,128)
    }
    if (tid < 64) b1s[tid] = b1[tid];
    __syncthreads();

    unsigned long long w2[16];
    #pragma unroll
    for (int kk = 0; kk < 16; ++kk) {
        const float lo = sm.w1s[j * 129 + g * 32 + 2 * kk];
        const float hi = sm.w1s[j * 129 + g * 32 + 2 * kk + 1];
        asm("mov.b64 %0, {%1, %2};" : "=l"(w2[kk]) : "f"(lo), "f"(hi));
    }
    __syncthreads();                                // w1s dead; union reused

    const int stride = MLPGRID * 4;
    const int base0  = blockIdx.x * 4;

    // fill iter 0; prime ids for iter 1
    int   nodeA = 0;
    float cntA  = 1.0f;
    {
        const int b = base0 + r;
        const int nd = nodes[b];
        sm.run.comb[0][r][j]      = __ldcg(&features[(size_t)nd * EMBED + j]);
        sm.run.comb[0][r][64 + j] = G_ACC[b * EMBED + j];       // raw sum
        if (j == 0) sm.run.invs[0][r] = 1.0f / fmaxf(G_CNT[b], 1.0f);
        const int p1 = base0 + stride;
        if (p1 < BATCH) { nodeA = nodes[p1 + r]; cntA = G_CNT[p1 + r]; }
    }
    __syncthreads();

    int cur = 0;
    for (int base = base0; base < BATCH; base += stride) {
        const int base1 = base + stride;
        const int base2 = base + 2 * stride;

        // issue next-iter loads (overlap the FMA block below)
        float fN = 0.0f, aN = 0.0f;
        if (base1 < BATCH) {
            fN = __ldcg(&features[(size_t)nodeA * EMBED + j]);
            aN = G_ACC[(base1 + r) * EMBED + j];                // raw sum
        }
        int   nodeB = 0;
        float cntB  = 1.0f;
        if (base2 < BATCH) { nodeB = nodes[base2 + r]; cntB = G_CNT[base2 + r]; }

        // partials from comb[cur]; neigh k-groups (g>=2) scaled by inv
        #pragma unroll
        for (int rr = 0; rr < 4; ++rr) {
            const ulonglong2* c2 = (const ulonglong2*)&sm.run.comb[cur][rr][g * 32];
            unsigned long long acc = 0ull;          // packed {0.f, 0.f}
            #pragma unroll
            for (int q = 0; q < 8; ++q) {           // 8 x LDS.128 broadcast
                const ulonglong2 c = c2[q];
                asm("fma.rn.f32x2 %0, %1, %2, %0;"
                    : "+l"(acc) : "l"(c.x), "l"(w2[2 * q]));
                asm("fma.rn.f32x2 %0, %1, %2, %0;"
                    : "+l"(acc) : "l"(c.y), "l"(w2[2 * q + 1]));
            }
            float lo, hi;
            asm("mov.b64 {%0, %1}, %2;" : "=f"(lo), "=f"(hi) : "l"(acc));
            const float m = (g >= 2) ? sm.run.invs[cur][rr] : 1.0f;
            sm.run.part[rr][j * 5 + g] = (lo + hi) * m;   // conflict-free
        }
        __syncthreads();

        {
            const float s = sm.run.part[r][j * 5 + 0] + sm.run.part[r][j * 5 + 1] +
                            sm.run.part[r][j * 5 + 2] + sm.run.part[r][j * 5 + 3] +
                            b1s[j];
            out[(size_t)(base + r) * EMBED + j] = fmaxf(s, 0.0f);
        }
        if (base1 < BATCH) {
            sm.run.comb[cur ^ 1][r][j]      = fN;
            sm.run.comb[cur ^ 1][r][64 + j] = aN;
            if (j == 0) sm.run.invs[cur ^ 1][r] = 1.0f / fmaxf(cntA, 1.0f);
        }
        nodeA = nodeB;
        cntA  = cntB;
        __syncthreads();
        cur ^= 1;
    }

    // ---- tail: zero exactly the scratch rows this block consumed ----
    for (int base = base0; base < BATCH; base += stride) {
        G_ACC[(base + r) * EMBED + j] = 0.0f;       // coalesced, own rows only
        if (j == 0) G_CNT[base + r] = 0.0f;
    }
}

// ---------------------------------------------------------------------------
// Launch — [dummy, agg, dummy, mlp]: the dummies shift ncu's fixed
// skip-5/count-1 capture onto agg_kernel (finally profiling the dominant
// kernel). They cost ~2µs of launch overhead and will be removed next round.
// inputs: nodes(i32,16384) neigh_ids(i32,524288) seg_ids(i32,524288)
//         features(f32,64M) w1(f32,8192) b1(f32,64)   output: f32 (16384,64)
// ---------------------------------------------------------------------------
extern "C" void kernel_launch(void* const* d_in, const int* in_sizes, int n_in,
                              void* d_out, int out_size) {
    const int*   nodes     = (const int*)  d_in[0];
    const int*   neigh_ids = (const int*)  d_in[1];
    const int*   seg_ids   = (const int*)  d_in[2];
    const float* features  = (const float*)d_in[3];
    const float* w1        = (const float*)d_in[4];
    const float* b1        = (const float*)d_in[5];
    float*       out       = (float*)d_out;

    dummy_kernel<<<1, 32>>>();
    const int n_warps = N_EDGES / 32;             // 16384 warps, 2048 blocks
    agg_kernel<<<n_warps / 8, 256>>>(neigh_ids, seg_ids, features);
    dummy_kernel<<<1, 32>>>();
    mlp_kernel<<<MLPGRID, 256>>>(nodes, features, w1, b1, out);
}

// round 16
// speedup vs baseline: 1.0536x; 1.0536x over previous
#include <cuda_runtime.h>
#include <cuda_bf16.h>
#include <cstdint>

#define BATCH   16384
#define EMBED   64
#define N_EDGES 524288
#define FULL    0xffffffffu
#define MLPGRID 592

// Scratch: zero-initialized at module load; the MLP tail re-zeroes exactly
// the rows it consumed, so every launch/replay starts from zeros.
__device__ float g_scratch[BATCH * EMBED + BATCH];
#define G_ACC g_scratch
#define G_CNT (g_scratch + BATCH * EMBED)

// Feature-table loads with an L2 evict-last cache policy (createpolicy +
// ld.global.L2::cache_hint — the immediate .L2::evict_last modifier is
// 256-bit-only on sm_103a ptxas). The ~100MB unique-row working set (same
// rows every graph replay) then sticks in the 126MB L2 instead of being
// churned out by the streaming arrays between replays.
__device__ __forceinline__ uint64_t evict_last_policy() {
    uint64_t pol;
    asm("createpolicy.fractional.L2::evict_last.b64 %0, 1.0;" : "=l"(pol));
    return pol;
}
__device__ __forceinline__ float2 ldg_row_sticky(const float2* p, uint64_t pol) {
    float2 v;
    asm volatile("ld.global.L2::cache_hint.v2.f32 {%0, %1}, [%2], %3;"
                 : "=f"(v.x), "=f"(v.y) : "l"(p), "l"(pol));
    return v;
}
__device__ __forceinline__ float ldg_f_sticky(const float* p, uint64_t pol) {
    float v;
    asm volatile("ld.global.L2::cache_hint.f32 %0, [%1], %2;"
                 : "=f"(v) : "l"(p), "l"(pol));
    return v;
}

// ---------------------------------------------------------------------------
// Kernel 1 (R9 core — proven): warp owns 32 consecutive edges; ids coalesced
// (.cs, evict-first) + shfl broadcast; 8 independent 256B feature-row loads
// in flight (evict-last policy); register run-compression on sorted seg_ids,
// atomic flush only on segment change.
// ---------------------------------------------------------------------------
__global__ void agg_kernel(const int*   __restrict__ neigh_ids,
                           const int*   __restrict__ seg_ids,
                           const float* __restrict__ features) {
    const int warp = (blockIdx.x * blockDim.x + threadIdx.x) >> 5;
    const int lane = threadIdx.x & 31;
    const int e0 = warp * 32;

    const int my_seg = __ldcs(&seg_ids[e0 + lane]);
    const int my_nid = __ldcs(&neigh_ids[e0 + lane]);

    const float2* __restrict__ feats2 = (const float2*)features;
    const uint64_t pol = evict_last_policy();

    float2 acc = make_float2(0.0f, 0.0f);
    int cur = __shfl_sync(FULL, my_seg, 0);
    int runlen = 0;

    #pragma unroll
    for (int c = 0; c < 32; c += 8) {
        int    n[8], s[8];
        float2 v[8];
        #pragma unroll
        for (int u = 0; u < 8; ++u) n[u] = __shfl_sync(FULL, my_nid, c + u);
        #pragma unroll
        for (int u = 0; u < 8; ++u)
            v[u] = ldg_row_sticky(&feats2[(size_t)n[u] * 32 + lane], pol);
        #pragma unroll
        for (int u = 0; u < 8; ++u) s[u] = __shfl_sync(FULL, my_seg, c + u);
        #pragma unroll
        for (int u = 0; u < 8; ++u) {
            if (s[u] != cur) {            // warp-uniform (s is broadcast)
                atomicAdd(&G_ACC[cur * EMBED + 2 * lane],     acc.x);
                atomicAdd(&G_ACC[cur * EMBED + 2 * lane + 1], acc.y);
                if (lane == 0) atomicAdd(&G_CNT[cur], (float)runlen);
                acc = make_float2(0.0f, 0.0f);
                cur = s[u];
                runlen = 0;
            }
            acc.x += v[u].x;
            acc.y += v[u].y;
            ++runlen;
        }
    }
    atomicAdd(&G_ACC[cur * EMBED + 2 * lane],     acc.x);
    atomicAdd(&G_ACC[cur * EMBED + 2 * lane + 1], acc.y);
    if (lane == 0) atomicAdd(&G_CNT[cur], (float)runlen);
}

// ---------------------------------------------------------------------------
// Kernel 2 (R14 — proven): self gather + mean + [self|neigh] @ w1^T + b1,
// relu. Depth-1 pipeline, deferred mean-divide (raw G_ACC in load path,
// neigh k-groups scaled at partial stage), consumer tail zeroing,
// launch_bounds(256,4). Self-feature reads use the same evict-last policy.
// ---------------------------------------------------------------------------
__global__ void __launch_bounds__(256, 4)
mlp_kernel(const int*   __restrict__ nodes,
           const float* __restrict__ features,
           const float* __restrict__ w1,
           const float* __restrict__ b1,
           float*       __restrict__ out) {
    __shared__ union {
        float w1s[64 * 129];                        // staging (prologue only)
        struct {
            __align__(16) float comb[2][4][128];    // double-buffered concat
            float part[4][64 * 5];                  // stride-5 padded partials
            float invs[2][4];                       // per-row 1/max(cnt,1)
        } run;
    } sm;
    __shared__ float b1s[64];

    const int tid = threadIdx.x;
    const int g = tid >> 6;                         // k-group 0..3 (warp-uni)
    const int j = tid & 63;                         // output dim
    const int r = g;                                // row for fill/writeback
    const uint64_t pol = evict_last_policy();

    for (int idx = tid; idx < 64 * 128; idx += 256) {
        const int jj = idx >> 7;
        const int kk = idx & 127;
        sm.w1s[jj * 129 + kk] = w1[idx];            // w1 row-major (64,128)
    }
    if (tid < 64) b1s[tid] = b1[tid];
    __syncthreads();

    unsigned long long w2[16];
    #pragma unroll
    for (int kk = 0; kk < 16; ++kk) {
        const float lo = sm.w1s[j * 129 + g * 32 + 2 * kk];
        const float hi = sm.w1s[j * 129 + g * 32 + 2 * kk + 1];
        asm("mov.b64 %0, {%1, %2};" : "=l"(w2[kk]) : "f"(lo), "f"(hi));
    }
    __syncthreads();                                // w1s dead; union reused

    const int stride = MLPGRID * 4;
    const int base0  = blockIdx.x * 4;

    // fill iter 0; prime ids for iter 1
    int   nodeA = 0;
    float cntA  = 1.0f;
    {
        const int b = base0 + r;
        const int nd = nodes[b];
        sm.run.comb[0][r][j]      = ldg_f_sticky(&features[(size_t)nd * EMBED + j], pol);
        sm.run.comb[0][r][64 + j] = G_ACC[b * EMBED + j];       // raw sum
        if (j == 0) sm.run.invs[0][r] = 1.0f / fmaxf(G_CNT[b], 1.0f);
        const int p1 = base0 + stride;
        if (p1 < BATCH) { nodeA = nodes[p1 + r]; cntA = G_CNT[p1 + r]; }
    }
    __syncthreads();

    int cur = 0;
    for (int base = base0; base < BATCH; base += stride) {
        const int base1 = base + stride;
        const int base2 = base + 2 * stride;

        // issue next-iter loads (overlap the FMA block below)
        float fN = 0.0f, aN = 0.0f;
        if (base1 < BATCH) {
            fN = ldg_f_sticky(&features[(size_t)nodeA * EMBED + j], pol);
            aN = G_ACC[(base1 + r) * EMBED + j];                // raw sum
        }
        int   nodeB = 0;
        float cntB  = 1.0f;
        if (base2 < BATCH) { nodeB = nodes[base2 + r]; cntB = G_CNT[base2 + r]; }

        // partials from comb[cur]; neigh k-groups (g>=2) scaled by inv
        #pragma unroll
        for (int rr = 0; rr < 4; ++rr) {
            const ulonglong2* c2 = (const ulonglong2*)&sm.run.comb[cur][rr][g * 32];
            unsigned long long acc = 0ull;          // packed {0.f, 0.f}
            #pragma unroll
            for (int q = 0; q < 8; ++q) {           // 8 x LDS.128 broadcast
                const ulonglong2 c = c2[q];
                asm("fma.rn.f32x2 %0, %1, %2, %0;"
                    : "+l"(acc) : "l"(c.x), "l"(w2[2 * q]));
                asm("fma.rn.f32x2 %0, %1, %2, %0;"
                    : "+l"(acc) : "l"(c.y), "l"(w2[2 * q + 1]));
            }
            float lo, hi;
            asm("mov.b64 {%0, %1}, %2;" : "=f"(lo), "=f"(hi) : "l"(acc));
            const float m = (g >= 2) ? sm.run.invs[cur][rr] : 1.0f;
            sm.run.part[rr][j * 5 + g] = (lo + hi) * m;   // conflict-free
        }
        __syncthreads();

        {
            const float s = sm.run.part[r][j * 5 + 0] + sm.run.part[r][j * 5 + 1] +
                            sm.run.part[r][j * 5 + 2] + sm.run.part[r][j * 5 + 3] +
                            b1s[j];
            out[(size_t)(base + r) * EMBED + j] = fmaxf(s, 0.0f);
        }
        if (base1 < BATCH) {
            sm.run.comb[cur ^ 1][r][j]      = fN;
            sm.run.comb[cur ^ 1][r][64 + j] = aN;
            if (j == 0) sm.run.invs[cur ^ 1][r] = 1.0f / fmaxf(cntA, 1.0f);
        }
        nodeA = nodeB;
        cntA  = cntB;
        __syncthreads();
        cur ^= 1;
    }

    // ---- tail: zero exactly the scratch rows this block consumed ----
    for (int base = base0; base < BATCH; base += stride) {
        G_ACC[(base + r) * EMBED + j] = 0.0f;       // coalesced, own rows only
        if (j == 0) G_CNT[base + r] = 0.0f;
    }
}

// ---------------------------------------------------------------------------
// Launch — two kernels.
// inputs: nodes(i32,16384) neigh_ids(i32,524288) seg_ids(i32,524288)
//         features(f32,64M) w1(f32,8192) b1(f32,64)   output: f32 (16384,64)
// ---------------------------------------------------------------------------
extern "C" void kernel_launch(void* const* d_in, const int* in_sizes, int n_in,
                              void* d_out, int out_size) {
    const int*   nodes     = (const int*)  d_in[0];
    const int*   neigh_ids = (const int*)  d_in[1];
    const int*   seg_ids   = (const int*)  d_in[2];
    const float* features  = (const float*)d_in[3];
    const float* w1        = (const float*)d_in[4];
    const float* b1        = (const float*)d_in[5];
    float*       out       = (float*)d_out;

    const int n_warps = N_EDGES / 32;             // 16384 warps, 2048 blocks
    agg_kernel<<<n_warps / 8, 256>>>(neigh_ids, seg_ids, features);

    mlp_kernel<<<MLPGRID, 256>>>(nodes, features, w1, b1, out);
}